// round 14
// baseline (speedup 1.0000x reference)
#include <cuda_runtime.h>
#include <cuda_fp16.h>
#include <cstdint>

// ============================================================================
// Problem constants
// ============================================================================
#define BATCH    4096
#define INPUTDIM 256
#define OUTDIM   256
#define GRIDSZ   64
#define KDIM     32768            // k = cs*16384 + i*64 + g
#define NPAIR    256              // loop over i; pair = (cos chunk i, sin chunk i)
#define MTILE    128
#define NTILE    64
#define MTILES   (BATCH / MTILE)  // 32
#define NTILES   (OUTDIM / NTILE) // 4
#define NTHREADS 384
#define NCONS    256              // consumer threads (warps 0-7)
#define NPROD    128              // producer threads (warps 8-11)

// SMEM stage (fp16, single product): A buffers cos,sin (128 rows x 128B),
// B buffers cos,sin (64 rows x 128B); rows padded to 144 B
// (144 % 16 == 0 for STS.128/cp.async; r*144 mod 128 = r*16 -> conflict-free)
#define ROWB     144
#define ABUF     (128 * ROWB)     // 18432
#define BBUF     (64 * ROWB)      // 9216
#define OFF_B0   (2 * ABUF)       // 36864
#define STAGEB   (2 * ABUF + 2 * BBUF)   // 55296
#define NSTAGE   4
#define SM_BAR   (NSTAGE * STAGEB)       // 221184
#define SMEM_BYTES (SM_BAR + 96)

// ============================================================================
// Scratch (device globals — no allocation allowed)
// ============================================================================
__device__ __half g_Bf16[(size_t)OUTDIM * KDIM];   // B as fp16, K-major

// ============================================================================
// Helpers
// ============================================================================
__device__ __forceinline__ uint32_t smem_to_u32(const void* p) {
    uint32_t a;
    asm("{ .reg .u64 t; cvta.to.shared.u64 t, %1; cvt.u32.u64 %0, t; }"
        : "=r"(a) : "l"(p));
    return a;
}

__device__ __forceinline__ void cp_async16(uint32_t dst, const void* src) {
    asm volatile("cp.async.cg.shared.global [%0], [%1], 16;"
                 :: "r"(dst), "l"(src) : "memory");
}

__device__ __forceinline__ void ldsm_x4(uint32_t r[4], uint32_t addr) {
    asm volatile("ldmatrix.sync.aligned.m8n8.x4.shared.b16 {%0,%1,%2,%3}, [%4];"
                 : "=r"(r[0]), "=r"(r[1]), "=r"(r[2]), "=r"(r[3]) : "r"(addr));
}

// fp16 MMA m16n8k16, fp32 accumulate
__device__ __forceinline__ void hmma16816(float acc[4], const uint32_t a[4],
                                          uint32_t b0, uint32_t b1) {
    asm volatile(
        "mma.sync.aligned.m16n8k16.row.col.f32.f16.f16.f32 "
        "{%0,%1,%2,%3}, {%4,%5,%6,%7}, {%8,%9}, {%0,%1,%2,%3};"
        : "+f"(acc[0]), "+f"(acc[1]), "+f"(acc[2]), "+f"(acc[3])
        : "r"(a[0]), "r"(a[1]), "r"(a[2]), "r"(a[3]), "r"(b0), "r"(b1));
}

#define MBAR_INIT(addr, cnt) \
    asm volatile("mbarrier.init.shared.b64 [%0], %1;" \
                 :: "r"((uint32_t)(addr)), "r"((uint32_t)(cnt)) : "memory")

#define MBAR_ARRIVE(addr) \
    asm volatile("mbarrier.arrive.shared.b64 _, [%0];" \
                 :: "r"((uint32_t)(addr)) : "memory")

#define MBAR_WAIT(addr, parity) do { \
    uint32_t _m = (uint32_t)(addr), _p = (uint32_t)(parity), _d; \
    asm volatile( \
        "{\n\t.reg .pred p;\n\t" \
        "mbarrier.try_wait.parity.acquire.cta.shared::cta.b64 p, [%1], %2;\n\t" \
        "selp.b32 %0, 1, 0, p;\n\t}" \
        : "=r"(_d) : "r"(_m), "r"(_p) : "memory"); \
    if (!_d) { \
        asm volatile( \
            "{\n\t.reg .pred P1;\n\t" \
            "WL_%=:\n\t" \
            "mbarrier.try_wait.parity.acquire.cta.shared::cta.b64 P1, [%0], %1, 0x989680;\n\t" \
            "@P1 bra.uni WD_%=;\n\t" \
            "bra.uni WL_%=;\n\t" \
            "WD_%=:\n\t}" \
            :: "r"(_m), "r"(_p) : "memory"); \
    } \
} while (0)

// ============================================================================
// Kernel 1: prep — fouriercoeffs f32 -> K-major fp16
// ============================================================================
__global__ void prep_kernel(const float* __restrict__ cf) {
    size_t idx = (size_t)blockIdx.x * 256 + threadIdx.x;
    if (idx >= (size_t)OUTDIM * KDIM) return;
    int o = (int)(idx >> 15);            // KDIM = 2^15
    int k = (int)(idx & (KDIM - 1));
    int cs = k >> 14;
    int i  = (k >> 6) & (INPUTDIM - 1);
    int g  = k & (GRIDSZ - 1);
    float v = cf[(((size_t)cs * OUTDIM + o) * INPUTDIM + i) * GRIDSZ + g];
    g_Bf16[idx] = __float2half_rn(v);
}

// ============================================================================
// Kernel 2: warp-specialized fused fp16 GEMM — single product (A16 x B16)
//   128 CTAs (32 M x 4 N), 384 threads:
//     warps 0-7  : consumers — warp (wm2, wn2, wq): 64(M) x 32(N) tile of the
//                  cos (wq=0) or sin (wq=1) half
//     warps 8-11 : producers — thread=row; DUAL interleaved rotation chains
//                  (odd/even freqs, double-angle step) halve serial latency;
//                  fp16 pack STS.128; B fp16 via cp.async
//   4-stage mbarrier ring (proven protocol: producer phase init 1).
// ============================================================================
__global__ void __launch_bounds__(NTHREADS, 1)
fourier_gemm(const float* __restrict__ x, const float* __restrict__ bias,
             float* __restrict__ out) {
    extern __shared__ char smem[];
    const uint32_t su32 = smem_to_u32(smem);
    const int tid = threadIdx.x;
    const int lid = tid & 31, wid = tid >> 5;
    const int mtile = blockIdx.x & (MTILES - 1);
    const int ntile = blockIdx.x >> 5;

    // barriers: full[0..3] at SM_BAR, empty[0..3] at SM_BAR+32
    const uint32_t barb = su32 + SM_BAR;
    if (tid == 0) {
        #pragma unroll
        for (int s = 0; s < NSTAGE; ++s) {
            MBAR_INIT(barb + s * 8,      NPROD);   // full
            MBAR_INIT(barb + 32 + s * 8, NCONS);   // empty
        }
    }
    __syncthreads();

    if (tid < NCONS) {
        // ==================== CONSUMER (warps 0-7) ====================
        const int wm2 = wid & 1;                  // M 64-row half
        const int wn2 = (wid >> 1) & 1;           // N 32-col half
        const int wq  = wid >> 2;                 // 0 = cos, 1 = sin
        const int mat = lid >> 3, mr = lid & 7;
        const uint32_t a_off =
            (uint32_t)((wm2 * 64 + (mat & 1) * 8 + mr) * ROWB + (mat >> 1) * 16);
        const uint32_t b_off =
            (uint32_t)((wn2 * 32 + (mat >> 1) * 8 + mr) * ROWB + (mat & 1) * 16);

        const uint32_t offA = wq ? ABUF : 0;
        const uint32_t offB = OFF_B0 + wq * BBUF;

        float acc[4][4][4];
        #pragma unroll
        for (int mt = 0; mt < 4; ++mt)
            #pragma unroll
            for (int nt = 0; nt < 4; ++nt)
                #pragma unroll
                for (int q = 0; q < 4; ++q) acc[mt][nt][q] = 0.f;

        int s = 0, pf = 0;
        for (int it = 0; it < NPAIR; ++it) {
            MBAR_WAIT(barb + s * 8, pf);
            const uint32_t sbase = su32 + s * STAGEB;
            const uint32_t aB = sbase + offA + a_off;
            const uint32_t bB = sbase + offB + b_off;

            #pragma unroll
            for (int ks = 0; ks < 4; ++ks) {
                const uint32_t ko = ks * 32;
                uint32_t Af[4][4], Bf[2][4];
                #pragma unroll
                for (int mt = 0; mt < 4; ++mt)
                    ldsm_x4(Af[mt], aB + mt * 16 * ROWB + ko);
                #pragma unroll
                for (int ng = 0; ng < 2; ++ng)
                    ldsm_x4(Bf[ng], bB + ng * 16 * ROWB + ko);
                #pragma unroll
                for (int mt = 0; mt < 4; ++mt)
                    #pragma unroll
                    for (int ng = 0; ng < 2; ++ng) {
                        hmma16816(acc[mt][ng * 2],     Af[mt], Bf[ng][0], Bf[ng][1]);
                        hmma16816(acc[mt][ng * 2 + 1], Af[mt], Bf[ng][2], Bf[ng][3]);
                    }
            }
            MBAR_ARRIVE(barb + 32 + s * 8);
            if (++s == NSTAGE) { s = 0; pf ^= 1; }
        }

        // ---- epilogue: merge cos(q=0) + sin(q=1) via smem scratch ----
        asm volatile("bar.sync 1, %0;" :: "n"(NCONS) : "memory");
        {
            const int fl = (wn2 * 2 + wm2) * 32 + lid;     // 0..127
            float* scr = (float*)(smem) + (size_t)fl * 68; // 68-float stride
            if (wq == 1) {
                #pragma unroll
                for (int mt = 0; mt < 4; ++mt)
                    #pragma unroll
                    for (int nt = 0; nt < 4; ++nt)
                        *(float4*)(scr + (mt * 4 + nt) * 4) =
                            make_float4(acc[mt][nt][0], acc[mt][nt][1],
                                        acc[mt][nt][2], acc[mt][nt][3]);
            }
            asm volatile("bar.sync 1, %0;" :: "n"(NCONS) : "memory");
            if (wq == 0) {
                #pragma unroll
                for (int mt = 0; mt < 4; ++mt) {
                    int r0 = mtile * MTILE + wm2 * 64 + mt * 16 + (lid >> 2);
                    #pragma unroll
                    for (int nt = 0; nt < 4; ++nt) {
                        float4 o2 = *(float4*)(scr + (mt * 4 + nt) * 4);
                        int c0 = ntile * NTILE + wn2 * 32 + nt * 8 + (lid & 3) * 2;
                        float b0 = __ldg(bias + c0);
                        float b1 = __ldg(bias + c0 + 1);
                        *(float2*)(out + (size_t)r0 * OUTDIM + c0) =
                            make_float2(acc[mt][nt][0] + o2.x + b0,
                                        acc[mt][nt][1] + o2.y + b1);
                        *(float2*)(out + (size_t)(r0 + 8) * OUTDIM + c0) =
                            make_float2(acc[mt][nt][2] + o2.z + b0,
                                        acc[mt][nt][3] + o2.w + b1);
                    }
                }
            }
        }
    } else {
        // ==================== PRODUCER (warps 8-11) ====================
        const int ptid = tid - NCONS;               // 0..127 == row
        const int fb = ptid;
        const float* xrow = x + (size_t)(mtile * MTILE + fb) * INPUTDIM;
        const char* bfp = (const char*)g_Bf16;

        int s = 0, pe = 1;                          // phase init 1 (proven)
        for (int it = 0; it < NPAIR; ++it) {
            MBAR_WAIT(barb + 32 + s * 8, pe);
            const uint32_t sbase = su32 + s * STAGEB;

            // ---- B tiles: 2 buffers (cos, sin), 16 KB ----
            #pragma unroll
            for (int q = 0; q < 8; ++q) {
                int idx = ptid + q * NPROD;          // 0..1023 segs of 16B
                int buf = idx >> 9;                  // 0..1 (= cs)
                int r   = (idx >> 3) & 63;
                int seg = idx & 7;
                uint32_t dst = sbase + OFF_B0 + buf * BBUF + r * ROWB + seg * 16;
                const char* src = bfp
                    + (size_t)(ntile * NTILE + r) * (KDIM * 2)
                    + (size_t)buf * 32768 + (size_t)it * 128 + seg * 16;
                cp_async16(dst, src);
            }
            asm volatile("cp.async.commit_group;" ::: "memory");

            // ---- A: DUAL rotation chains (odd/even freq, 2x step) ----
            {
                float xv = __ldg(xrow + it);
                float S, C;
                sincosf(xv, &S, &C);
                // double-angle step
                float C2 = __fmaf_rn(C, C, -S * S);   // cos 2x
                float S2 = 2.f * C * S;               // sin 2x
                // chain A: odd freqs 1,3,5,...  chain B: even freqs 2,4,6,...
                float ca = C,  sa = S;                // freq 1
                float cb = C2, sb = S2;               // freq 2

                char* pc = smem + s * STAGEB + fb * ROWB;   // cos
                char* ps = pc + ABUF;                       // sin

                #pragma unroll
                for (int w = 0; w < 8; ++w) {
                    uint32_t wc[4], ws[4];
                    #pragma unroll
                    for (int p = 0; p < 4; ++p) {
                        // pack (odd freq, even freq) — the two chain heads
                        __half2 hc = __floats2half2_rn(ca, cb);
                        __half2 hs = __floats2half2_rn(sa, sb);
                        wc[p] = *(uint32_t*)&hc;
                        ws[p] = *(uint32_t*)&hs;
                        // step both chains by 2x (independent -> overlap)
                        float ca2 = ca * C2 - sa * S2;
                        float sa2 = sa * C2 + ca * S2;
                        float cb2 = cb * C2 - sb * S2;
                        float sb2 = sb * C2 + cb * S2;
                        ca = ca2; sa = sa2; cb = cb2; sb = sb2;
                    }
                    *(uint4*)(pc + w * 16) = make_uint4(wc[0], wc[1], wc[2], wc[3]);
                    *(uint4*)(ps + w * 16) = make_uint4(ws[0], ws[1], ws[2], ws[3]);
                }
            }

            asm volatile("cp.async.wait_group 0;" ::: "memory");
            MBAR_ARRIVE(barb + s * 8);
            if (++s == NSTAGE) { s = 0; pe ^= 1; }
        }
    }
}

// ============================================================================
// Launch
// ============================================================================
extern "C" void kernel_launch(void* const* d_in, const int* in_sizes, int n_in,
                              void* d_out, int out_size) {
    const float* x    = (const float*)d_in[0];
    const float* cf   = (const float*)d_in[1];
    const float* bias = (const float*)d_in[2];
    float* out = (float*)d_out;

    cudaFuncSetAttribute(fourier_gemm,
                         cudaFuncAttributeMaxDynamicSharedMemorySize, SMEM_BYTES);

    prep_kernel<<<(OUTDIM * KDIM + 255) / 256, 256>>>(cf);
    fourier_gemm<<<MTILES * NTILES, NTHREADS, SMEM_BYTES>>>(x, bias, out);
    (void)in_sizes; (void)n_in; (void)out_size;
}